// round 17
// baseline (speedup 1.0000x reference)
#include <cuda_runtime.h>
#include <cuda_fp16.h>
#include <cstdint>

#define NHEAD 12
#define NB    64
#define NTOK  577
#define NC    768
#define ND    64
#define NKEEP 289          // tokens kept incl. CLS
#define NMASK 576
#define MROWS (NB*NTOK)    // 36928
#define QCOLS (3*NC)       // 2304
#define NT8   37           // n-tiles of 8
#define NPAD2 304          // padded kept tokens (19 x 16)
#define NKT   48           // 768/16 k-tiles

// ---------------- scratch (static device globals; no allocations) -------------
__device__ __align__(16) __half g_xh  [(size_t)MROWS*NC];          // x as half
__device__ __align__(16) __half g_wqkvh[(size_t)NC*QCOLS];         // Wqkv half
__device__ __align__(16) __half g_wprojh[(size_t)NC*NC];           // Wproj half
__device__ __align__(16) __half g_qh [(size_t)NB*NHEAD*NTOK*ND];   // Q half
__device__ __align__(16) __half g_kph[(size_t)NB*NHEAD*NKEEP*ND];  // gathered K half
__device__ __align__(16) __half g_vph[(size_t)NB*NHEAD*NKEEP*ND];  // gathered V half
__device__ __align__(16) __half g_aoh[(size_t)NB*NTOK*NC];         // attn out half
__device__ int g_dest[NB*NHEAD*NTOK];                              // token -> kept slot

// ---------------- helpers ------------------------------------------------------
__device__ __forceinline__ void mma_f16(float* c, const uint32_t* a, const uint32_t* b) {
    asm volatile(
        "mma.sync.aligned.m16n8k16.row.col.f32.f16.f16.f32 "
        "{%0,%1,%2,%3}, {%4,%5,%6,%7}, {%8,%9}, {%0,%1,%2,%3};\n"
        : "+f"(c[0]), "+f"(c[1]), "+f"(c[2]), "+f"(c[3])
        : "r"(a[0]), "r"(a[1]), "r"(a[2]), "r"(a[3]), "r"(b[0]), "r"(b[1]));
}
__device__ __forceinline__ void ldsm_x4(uint32_t* r, uint32_t addr) {
    asm volatile("ldmatrix.sync.aligned.m8n8.x4.shared.b16 {%0,%1,%2,%3}, [%4];"
                 : "=r"(r[0]), "=r"(r[1]), "=r"(r[2]), "=r"(r[3]) : "r"(addr));
}
__device__ __forceinline__ void ldsm_x2_trans(uint32_t& r0, uint32_t& r1, uint32_t addr) {
    asm volatile("ldmatrix.sync.aligned.m8n8.x2.trans.shared.b16 {%0,%1}, [%2];"
                 : "=r"(r0), "=r"(r1) : "r"(addr));
}
__device__ __forceinline__ uint32_t smem_u32(const void* p) {
    return (uint32_t)__cvta_generic_to_shared(p);
}
__device__ __forceinline__ void cp16(uint32_t dst, const void* src, bool pred) {
    int sz = pred ? 16 : 0;
    asm volatile("cp.async.cg.shared.global [%0], [%1], 16, %2;\n"
                 :: "r"(dst), "l"(src), "r"(sz));
}
__device__ __forceinline__ void cp_commit() {
    asm volatile("cp.async.commit_group;\n" ::: "memory");
}
__device__ __forceinline__ void cp_wait1() {
    asm volatile("cp.async.wait_group 1;\n" ::: "memory");
}

// ---------------- fused fp32 -> fp16 convert (3 tensors, 1 launch) -------------
__global__ __launch_bounds__(256) void f2h3_kernel(const float* __restrict__ a,
                                                   const float* __restrict__ b,
                                                   const float* __restrict__ c,
                                                   int na, int nb, int nc)
{
    long i = ((long)blockIdx.x * 256 + threadIdx.x) * 4;
    const float* src; __half* dst; long off;
    if (i < na)            { src = a; dst = g_xh;     off = i; }
    else if (i < na + nb)  { src = b; dst = g_wqkvh;  off = i - na; }
    else if (i < na + nb + nc) { src = c; dst = g_wprojh; off = i - na - nb; }
    else return;
    float4 v = *(const float4*)(src + off);
    __half2 p = __floats2half2_rn(v.x, v.y);
    __half2 q = __floats2half2_rn(v.z, v.w);
    *(uint2*)(dst + off) = make_uint2(*(uint32_t*)&p, *(uint32_t*)&q);
}

// ---------------- token selection: uint64 keys + parallel scan -----------------
__global__ __launch_bounds__(256) void select_kernel(const float* __restrict__ mask)
{
    int row = blockIdx.x;                       // b*NHEAD + h
    __shared__ __align__(16) unsigned long long key[NMASK];
    __shared__ unsigned char keep[NMASK];
    __shared__ int wsum[8];
    int tid = threadIdx.x;
    const float* mrow = mask + (size_t)row * NMASK;
    for (int i = tid; i < NMASK; i += 256) {
        uint32_t fb = __float_as_uint(mrow[i]);   // uniform [0,1): bit-monotonic
        key[i] = ((unsigned long long)fb << 32) | (uint32_t)(NMASK - 1 - i);
    }
    __syncthreads();
    for (int i = tid; i < NMASK; i += 256) {
        unsigned long long ki = key[i];
        int cnt = 0;
        #pragma unroll 4
        for (int j = 0; j < NMASK; j += 2) {
            ulonglong2 kj = *(const ulonglong2*)&key[j];
            cnt += (kj.x > ki) + (kj.y > ki);
        }
        keep[i] = (cnt < (NKEEP - 1)) ? 1 : 0;
    }
    __syncthreads();
    // parallel prefix over 576 = 192 x 3
    int lane = tid & 31, w = tid >> 5;
    int s0 = 0, s1 = 0, s2 = 0, base3 = tid * 3;
    if (tid < 192) { s0 = keep[base3]; s1 = keep[base3+1]; s2 = keep[base3+2]; }
    int mysum = s0 + s1 + s2;
    int v = mysum;
    #pragma unroll
    for (int o = 1; o < 32; o <<= 1) {
        int n = __shfl_up_sync(0xffffffffu, v, o);
        if (lane >= o) v += n;
    }
    if (lane == 31) wsum[w] = v;
    __syncthreads();
    if (tid == 0) {
        int acc = 0;
        #pragma unroll
        for (int i = 0; i < 8; ++i) { int t = wsum[i]; wsum[i] = acc; acc += t; }
    }
    __syncthreads();
    if (tid < 192) {
        int excl = v - mysum + wsum[w];
        int* dm = g_dest + (size_t)row * NTOK;
        if (tid == 0) dm[0] = 0;
        int pos = excl;
        pos += s0; dm[1 + base3 + 0] = s0 ? pos : -1;
        pos += s1; dm[1 + base3 + 1] = s1 ? pos : -1;
        pos += s2; dm[1 + base3 + 2] = s2 ? pos : -1;
    }
}

// ---------------- 128x128x16 fp16 GEMM, 3-stage cp.async (R15, proven) ----------
#define AS_H 40
#define BS_H 136
template<int LDW, bool SCATTER>
__global__ __launch_bounds__(256, 2) void gemm_cp(const __half* __restrict__ A,
                                                  const __half* __restrict__ W,
                                                  const float* __restrict__ bias,
                                                  float* __restrict__ out)
{
    __shared__ __half As[3][128][AS_H];
    __shared__ __half Bs[3][16][BS_H];

    int tid  = threadIdx.x;
    int brow = blockIdx.y * 128;
    int bcol = blockIdx.x * 128;

    int arow = tid >> 1;
    int acol = (tid & 1) << 3;
    int brw  = tid >> 4;
    int bcl  = (tid & 15) << 3;
    bool aok = (brow + arow) < MROWS;
    const __half* Ap = A + (size_t)(brow + arow) * NC + acol;
    const __half* Wp = W + (size_t)brw * LDW + bcol + bcl;

    int wid  = tid >> 5;
    int lane = tid & 31;
    int gid  = lane >> 2;
    int tid4 = lane & 3;
    int m0 = (wid >> 2) * 64;
    int n0 = (wid & 3) * 32;
    int la_row = lane & 15;
    int la_col = (lane >> 4) << 3;
    int lrowB  = (lane & 7) + ((lane >> 3) & 1) * 8;

    uint32_t as_addr[3], bs_addr[3];
    #pragma unroll
    for (int s = 0; s < 3; ++s) {
        as_addr[s] = smem_u32(&As[s][arow][acol]);
        bs_addr[s] = smem_u32(&Bs[s][brw][bcl]);
    }

    #pragma unroll
    for (int s = 0; s < 2; ++s) {
        cp16(as_addr[s], Ap + s * 16, aok);
        cp16(bs_addr[s], Wp + (size_t)(s * 16) * LDW, true);
        cp_commit();
    }

    float c[4][4][4];
    #pragma unroll
    for (int mt = 0; mt < 4; ++mt)
        #pragma unroll
        for (int nt = 0; nt < 4; ++nt)
            #pragma unroll
            for (int r = 0; r < 4; ++r) c[mt][nt][r] = 0.f;

    for (int t = 0; t < NKT; ++t) {
        cp_wait1();
        __syncthreads();
        if (t + 2 < NKT) {
            int s = (t + 2) % 3;
            cp16(as_addr[s], Ap + (t + 2) * 16, aok);
            cp16(bs_addr[s], Wp + (size_t)((t + 2) * 16) * LDW, true);
        }
        cp_commit();

        int s = t % 3;
        uint32_t asb = smem_u32(&As[s][0][0]);
        uint32_t bsb = smem_u32(&Bs[s][0][0]);
        uint32_t af[4][4], bf[4][2];
        #pragma unroll
        for (int mt = 0; mt < 4; ++mt)
            ldsm_x4(af[mt], asb + (uint32_t)(((m0 + mt*16 + la_row) * AS_H + la_col) * 2));
        #pragma unroll
        for (int nt = 0; nt < 4; ++nt)
            ldsm_x2_trans(bf[nt][0], bf[nt][1],
                          bsb + (uint32_t)((lrowB * BS_H + n0 + nt * 8) * 2));
        #pragma unroll
        for (int mt = 0; mt < 4; ++mt)
            #pragma unroll
            for (int nt = 0; nt < 4; ++nt)
                mma_f16(c[mt][nt], af[mt], bf[nt]);
        __syncthreads();
    }

    int colbase = bcol + n0;
    int s  = colbase / NC;
    int hd = colbase - s * NC;
    int h  = hd >> 6;

    #pragma unroll
    for (int mt = 0; mt < 4; ++mt) {
        #pragma unroll
        for (int half = 0; half < 2; ++half) {
            int m = brow + m0 + mt * 16 + gid + half * 8;
            if (m >= MROWS) continue;
            if (SCATTER) {
                int b  = m / NTOK;
                int n  = m - b * NTOK;
                int bh = b * NHEAD + h;
                __half* dst = nullptr;
                if (s == 0) {
                    dst = &g_qh[((size_t)bh * NTOK + n) * ND];
                } else {
                    int dest = g_dest[bh * NTOK + n];
                    if (dest >= 0)
                        dst = &((s == 1) ? g_kph : g_vph)[((size_t)bh * NKEEP + dest) * ND];
                }
                if (!dst) continue;
                int d_off = hd & 63;
                #pragma unroll
                for (int nt = 0; nt < 4; ++nt) {
                    int cl = nt * 8 + tid4 * 2;
                    float2 bv = *(const float2*)(bias + colbase + cl);
                    *(__half2*)(dst + d_off + cl) =
                        __floats2half2_rn(c[mt][nt][half*2+0] + bv.x,
                                          c[mt][nt][half*2+1] + bv.y);
                }
            } else {
                float* dst = out + (size_t)m * LDW + colbase;
                #pragma unroll
                for (int nt = 0; nt < 4; ++nt) {
                    int cl = nt * 8 + tid4 * 2;
                    float2 bv = *(const float2*)(bias + colbase + cl);
                    float2 o;
                    o.x = c[mt][nt][half*2+0] + bv.x;
                    o.y = c[mt][nt][half*2+1] + bv.y;
                    *(float2*)(dst + cl) = o;
                }
            }
        }
    }
}

// ---------------- attention: paired-nt ldsm.x4 Phase A, half2 softmax ----------
#define QK_H 72
#define PS_H 312
#define ATTN_SMEM (32*QK_H*2 + NPAD2*QK_H*2 + NPAD2*QK_H*2 + 32*PS_H*2)

__global__ __launch_bounds__(256, 2) void attn_mma()
{
    extern __shared__ __align__(16) char sm[];
    __half* Qh = (__half*)sm;                          // 32 x 72
    __half* Kh = Qh + 32 * QK_H;                       // 304 x 72 (zero-padded)
    __half* Vh = Kh + NPAD2 * QK_H;                    // 304 x 72 (zero-padded)
    __half* Ps = Vh + NPAD2 * QK_H;                    // 32 x 312 (S then P)

    int tid  = threadIdx.x;
    int bh   = blockIdx.x;
    int wid  = tid >> 5;
    int lane = tid & 31;
    int gid  = lane >> 2;
    int t4   = lane & 3;

    int la_row = lane & 15;
    int la_col = (lane >> 4) << 3;
    // K pair-x4: 4 sub-matrices (rows nb/nb+8 x cols k0/k0+8)
    int kg = lane >> 3;                        // 0..3
    int kr = lane & 7;
    int k_roff = kr + ((kg >= 2) ? 8 : 0);
    int k_coff = (kg & 1) ? 8 : 0;

    const __half* kp = g_kph + (size_t)bh * NKEEP * ND;
    const __half* vp = g_vph + (size_t)bh * NKEEP * ND;
    const uint4 zu4 = make_uint4(0u, 0u, 0u, 0u);
    for (int idx = tid; idx < NPAD2 * 8; idx += 256) {
        int m = idx >> 3, ch = (idx & 7) << 3;
        uint4 vv = (m < NKEEP) ? *(const uint4*)(vp + (size_t)m * ND + ch) : zu4;
        *(uint4*)&Vh[m * QK_H + ch] = vv;
        uint4 kv = (m < NKEEP) ? *(const uint4*)(kp + (size_t)m * ND + ch) : zu4;
        *(uint4*)&Kh[m * QK_H + ch] = kv;
    }
    const __half* qp = g_qh + (size_t)bh * NTOK * ND;
    int b = bh / NHEAD, h = bh - b * NHEAD;
    uint32_t qh_base = smem_u32(Qh);
    uint32_t kh_base = smem_u32(Kh);
    uint32_t vh_base = smem_u32(Vh);
    uint32_t ps_base = smem_u32(Ps);

    for (int q0 = 0; q0 < NTOK; q0 += 32) {
        {
            int m = tid >> 3, ch = (tid & 7) << 3;
            int qg = q0 + m;
            uint4 qv = (qg < NTOK) ? *(const uint4*)(qp + (size_t)qg * ND + ch) : zu4;
            *(uint4*)&Qh[m * QK_H + ch] = qv;
        }
        __syncthreads();

        // Phase A: S = (Q K^T) * scale -> half into Ps; K via paired ldsm.x4
        {
            int wm = wid & 1, wn = wid >> 1;
            int m0 = wm * 16;
            float c[5][2][4];
            #pragma unroll
            for (int i = 0; i < 5; ++i)
                #pragma unroll
                for (int u = 0; u < 2; ++u)
                    c[i][u][0] = c[i][u][1] = c[i][u][2] = c[i][u][3] = 0.f;
            #pragma unroll
            for (int ks = 0; ks < 4; ++ks) {
                int k0 = ks * 16;
                uint32_t a[4];
                ldsm_x4(a, qh_base + (uint32_t)(((m0 + la_row) * QK_H + k0 + la_col) * 2));
                #pragma unroll
                for (int i = 0; i < 5; ++i) {
                    int p = wn + 4 * i;
                    if (p >= 19) break;
                    int nb = p * 16;
                    uint32_t bb[4];
                    ldsm_x4(bb, kh_base +
                        (uint32_t)(((nb + k_roff) * QK_H + k0 + k_coff) * 2));
                    mma_f16(c[i][0], a, bb + 0);
                    mma_f16(c[i][1], a, bb + 2);
                }
            }
            #pragma unroll
            for (int i = 0; i < 5; ++i) {
                int p = wn + 4 * i;
                if (p >= 19) break;
                #pragma unroll
                for (int u = 0; u < 2; ++u) {
                    int nb = p * 16 + u * 8;
                    *(__half2*)&Ps[(m0 + gid) * PS_H + nb + 2 * t4]
                        = __floats2half2_rn(c[i][u][0] * 0.125f, c[i][u][1] * 0.125f);
                    *(__half2*)&Ps[(m0 + gid + 8) * PS_H + nb + 2 * t4]
                        = __floats2half2_rn(c[i][u][2] * 0.125f, c[i][u][3] * 0.125f);
                }
            }
        }
        __syncthreads();

        // Phase B: 3-pass max-subtracted softmax, half2-vectorized, 1 exp/elem
        {
            int w = tid >> 5, ln = tid & 31;
            #pragma unroll
            for (int r = 0; r < 4; ++r) {
                __half*  Pr  = Ps + (w * 4 + r) * PS_H;
                __half2* Pr2 = (__half2*)Pr;
                float mx = -3.0e38f;
                for (int m2 = ln; m2 < 144; m2 += 32) {
                    float2 f = __half22float2(Pr2[m2]);
                    mx = fmaxf(mx, fmaxf(f.x, f.y));
                }
                if (ln == 0) mx = fmaxf(mx, __half2float(Pr[288]));
                #pragma unroll
                for (int o = 16; o; o >>= 1) mx = fmaxf(mx, __shfl_xor_sync(0xffffffffu, mx, o));
                float sum = 0.f;
                for (int m2 = ln; m2 < 144; m2 += 32) {
                    float2 f = __half22float2(Pr2[m2]);
                    float e0 = __expf(f.x - mx), e1 = __expf(f.y - mx);
                    Pr2[m2] = __floats2half2_rn(e0, e1);
                    sum += e0 + e1;
                }
                if (ln == 0) {
                    float e = __expf(__half2float(Pr[288]) - mx);
                    Pr[288] = __float2half(e);
                    sum += e;
                }
                #pragma unroll
                for (int o = 16; o; o >>= 1) sum += __shfl_xor_sync(0xffffffffu, sum, o);
                float inv = 1.f / sum;
                for (int m2 = ln; m2 < 144; m2 += 32) {
                    float2 f = __half22float2(Pr2[m2]);
                    Pr2[m2] = __floats2half2_rn(f.x * inv, f.y * inv);
                }
                if (ln == 0)
                    Pr[288] = __float2half(__half2float(Pr[288]) * inv);
            }
        }
        __syncthreads();

        // Phase C: O = P @ V; P via ldsm.x4, V via ldsm.x2.trans
        {
            int wm = wid & 1, wn = wid >> 1;
            int m0 = wm * 16, n0 = wn * 16;
            float c[2][4];
            #pragma unroll
            for (int nt = 0; nt < 2; ++nt)
                #pragma unroll
                for (int r = 0; r < 4; ++r) c[nt][r] = 0.f;

            int lrow = (lane & 7) + ((lane >> 3) & 1) * 8;

            for (int ks = 0; ks < NPAD2 / 16; ++ks) {
                int k0 = ks * 16;
                uint32_t a[4];
                ldsm_x4(a, ps_base + (uint32_t)(((m0 + la_row) * PS_H + k0 + la_col) * 2));
                #pragma unroll
                for (int nt = 0; nt < 2; ++nt) {
                    uint32_t bb[2];
                    uint32_t addr = vh_base + (uint32_t)(((k0 + lrow) * QK_H + n0 + nt * 8) * 2);
                    ldsm_x2_trans(bb[0], bb[1], addr);
                    mma_f16(c[nt], a, bb);
                }
            }

            #pragma unroll
            for (int half = 0; half < 2; ++half) {
                int qg = q0 + m0 + gid + half * 8;
                if (qg >= NTOK) continue;
                __half* dst = &g_aoh[((size_t)(b * NTOK + qg)) * NC + h * ND + n0];
                #pragma unroll
                for (int nt = 0; nt < 2; ++nt) {
                    *(__half2*)(dst + nt * 8 + 2 * t4) =
                        __floats2half2_rn(c[nt][half*2+0], c[nt][half*2+1]);
                }
            }
        }
        __syncthreads();
    }
}

// ---------------- launch -------------------------------------------------------
extern "C" void kernel_launch(void* const* d_in, const int* in_sizes, int n_in,
                              void* d_out, int out_size)
{
    const float* x     = (const float*)d_in[0];
    const float* mask  = (const float*)d_in[1];
    const float* Wqkv  = (const float*)d_in[2];
    const float* bqkv  = (const float*)d_in[3];
    const float* Wproj = (const float*)d_in[4];
    const float* bproj = (const float*)d_in[5];
    float* out = (float*)d_out;

    __half *xh, *wqkvh, *wprojh, *aoh;
    cudaGetSymbolAddress((void**)&xh,     g_xh);
    cudaGetSymbolAddress((void**)&wqkvh,  g_wqkvh);
    cudaGetSymbolAddress((void**)&wprojh, g_wprojh);
    cudaGetSymbolAddress((void**)&aoh,    g_aoh);

    {
        int n1 = MROWS * NC, n2 = NC * QCOLS, n3 = NC * NC;
        long total = (long)n1 + n2 + n3;
        f2h3_kernel<<<(int)((total / 4 + 255) / 256), 256>>>(x, Wqkv, Wproj, n1, n2, n3);
    }

    select_kernel<<<NB * NHEAD, 256>>>(mask);

    dim3 g1(QCOLS / 128, (MROWS + 127) / 128);
    gemm_cp<QCOLS, true><<<g1, 256>>>(xh, wqkvh, bqkv, nullptr);

    cudaFuncSetAttribute(attn_mma, cudaFuncAttributeMaxDynamicSharedMemorySize, ATTN_SMEM);
    attn_mma<<<NB * NHEAD, 256, ATTN_SMEM>>>();

    dim3 g2(NC / 128, (MROWS + 127) / 128);
    gemm_cp<NC, false><<<g2, 256>>>(aoh, wprojh, bproj, out);
}